// round 4
// baseline (speedup 1.0000x reference)
#include <cuda_runtime.h>
#include <cuda_bf16.h>

#define NC 50000
#define BATCH 128
#define ROWS 768                 // 6 parts * 128
#define DIM 1536                 // 6 * 256
#define NBLK 148                 // one block per SM: guaranteed co-resident
#define NTHR 256
#define N4Q 3125                 // float4 per quarter-row (50000/4/4)
#define TOTAL_ITEMS 3200         // 3072 row-quarters + 128 dist, 1-in-25 interleave

// ---------------- device scratch (no cudaMalloc allowed) ----------------
__device__ float g_part[ROWS][4][6];    // per-quarter partial stats
__device__ float g_tri[2 * BATCH];
__device__ float g_F[BATCH * DIM];      // normalized feat rows, fp32
__device__ __align__(16) __nv_bfloat16 g_TtB[DIM * 256]; // transposed targets
__device__ float g_n2[256];
__device__ unsigned g_work;             // work-steal counter (reset by block 0)
__device__ unsigned g_arrive;           // barrier arrivals (self-resetting)
__device__ unsigned g_release;          // barrier generation (monotonic)

__device__ __forceinline__ float ex2(float v) {
    float r;
    asm("ex2.approx.ftz.f32 %0, %1;" : "=f"(r) : "f"(v));
    return r;
}

// Generation-based grid barrier. Safe because all NBLK blocks are resident.
__device__ __forceinline__ void grid_barrier() {
    __syncthreads();
    if (threadIdx.x == 0) {
        unsigned gen = *((volatile unsigned*)&g_release);
        __threadfence();
        if (atomicAdd(&g_arrive, 1u) == NBLK - 1) {
            g_arrive = 0;                 // safe: nobody touches until released
            __threadfence();
            atomicAdd(&g_release, 1u);
        } else {
            while (*((volatile unsigned*)&g_release) == gen) { }
        }
        __threadfence();
    }
    __syncthreads();
}

struct SmemT {
    union {
        struct {
            float a0[DIM], a1[DIM];
            float red[8][2][128];
            float wmax[2][8], wmin[2][8];
        } d;
        float sm[6][8];
        float wsum[8];
        float fm[4][8];
    } u;
    int it;
};

__global__ __launch_bounds__(NTHR) void mega_kernel(
    const float* __restrict__ logits, const float* __restrict__ soft,
    const float* __restrict__ ew,     const int*   __restrict__ labels,
    const float* __restrict__ adv,    const int*   __restrict__ mod,
    const float* __restrict__ idf,    const float* __restrict__ gf,
    const int*   __restrict__ epoch_p, float* __restrict__ out)
{
    __shared__ SmemT s;
    const int tid = threadIdx.x;
    const int bid = blockIdx.x;
    const int lane = tid & 31, wid = tid >> 5;
    const unsigned full = 0xffffffffu;
    const float C = 0.48089834696298783f;   // log2(e)/3

    // ================= phase 1: prep (normalize + bf16 transpose) =========
    for (int j = bid; j < 256; j += NBLK) {
        const float* src = (j < BATCH) ? idf : gf;
        int b = j & (BATCH - 1);
        float v[6];
        float sq = 0.f;
#pragma unroll
        for (int p = 0; p < 6; p++) {
            float x = src[(size_t)(p * BATCH + b) * 256 + tid];
            v[p] = x;
            sq = fmaf(x, x, sq);
        }
#pragma unroll
        for (int off = 16; off; off >>= 1) sq += __shfl_down_sync(full, sq, off);
        if (lane == 0) s.u.wsum[wid] = sq;
        __syncthreads();
        float tot = 0.f;
#pragma unroll
        for (int w = 0; w < 8; w++) tot += s.u.wsum[w];
        float rn = rsqrtf(tot);
#pragma unroll
        for (int p = 0; p < 6; p++) {
            int d = p * 256 + tid;
            float nv = v[p] * rn;
            g_TtB[(size_t)d * 256 + j] = __float2bfloat16_rn(nv);
            if (j < BATCH) g_F[(size_t)b * DIM + d] = nv;
        }
        if (tid == 0) g_n2[j] = tot * rn * rn;
        __syncthreads();
    }

    grid_barrier();

    // ================= phase 2: work-stealing (rows + dist overlapped) ====
    while (true) {
        if (tid == 0) s.it = (int)atomicAdd(&g_work, 1u);
        __syncthreads();
        int it = s.it;
        if (it >= TOTAL_ITEMS) break;

        if (it % 25 == 0) {
            // ---------------- dist item: (anchor pair, target half) -------
            int d  = it / 25;
            int p  = d >> 1, h = d & 1;
            int i0 = p * 2;

            for (int dd = tid; dd < DIM; dd += NTHR) {
                s.u.d.a0[dd] = g_F[(size_t)i0 * DIM + dd];
                s.u.d.a1[dd] = g_F[(size_t)(i0 + 1) * DIM + dd];
            }
            __syncthreads();

            int slice = wid;            // 8 K-slices of 192
            int jg    = lane;           // 32 uint2 groups = 128 targets
            const uint2* T2 = (const uint2*)g_TtB;
            const uint2* Tp = T2 + (size_t)(slice * 192) * 64 + (h * 32 + jg);
            const int kbase = slice * 192;

            float c00 = 0.f, c01 = 0.f, c02 = 0.f, c03 = 0.f;
            float c10 = 0.f, c11 = 0.f, c12 = 0.f, c13 = 0.f;
#pragma unroll 1
            for (int kk = 0; kk < 192; kk += 16) {
                uint2 t[16];
                const uint2* Tq = Tp + (size_t)kk * 64;
#pragma unroll
                for (int u = 0; u < 16; u++) t[u] = Tq[u * 64];
#pragma unroll
                for (int u = 0; u < 16; u++) {
                    float f0 = __uint_as_float(t[u].x << 16);
                    float f1 = __uint_as_float(t[u].x & 0xffff0000u);
                    float f2 = __uint_as_float(t[u].y << 16);
                    float f3 = __uint_as_float(t[u].y & 0xffff0000u);
                    float A0 = s.u.d.a0[kbase + kk + u];
                    float A1 = s.u.d.a1[kbase + kk + u];
                    c00 = fmaf(A0, f0, c00); c01 = fmaf(A0, f1, c01);
                    c02 = fmaf(A0, f2, c02); c03 = fmaf(A0, f3, c03);
                    c10 = fmaf(A1, f0, c10); c11 = fmaf(A1, f1, c11);
                    c12 = fmaf(A1, f2, c12); c13 = fmaf(A1, f3, c13);
                }
            }
            ((float4*)s.u.d.red[slice][0])[jg] = make_float4(c00, c01, c02, c03);
            ((float4*)s.u.d.red[slice][1])[jg] = make_float4(c10, c11, c12, c13);
            __syncthreads();

            int a  = tid >> 7;          // 0/1 -> anchor i0 / i0+1
            int jl = tid & 127;
            int ia = i0 + a;
            int jglob = h * 128 + jl;

            float dot = 0.f;
#pragma unroll
            for (int sl = 0; sl < 8; sl++) dot += s.u.d.red[sl][a][jl];
            float sqv = g_n2[ia] + g_n2[jglob] - 2.f * dot;
            float dj  = sqrtf(fmaxf(sqv, 0.f) + 1e-12f);

            bool eq  = (labels[ia] == labels[jl]);
            bool pos = h ? eq : (eq && (jl != ia));
            float apv = pos   ? dj : -1e30f;
            float anv = (!eq) ? dj :  1e30f;
#pragma unroll
            for (int off = 16; off; off >>= 1) {
                apv = fmaxf(apv, __shfl_down_sync(full, apv, off));
                anv = fminf(anv, __shfl_down_sync(full, anv, off));
            }
            if (lane == 0) { s.u.d.wmax[a][wid & 3] = apv; s.u.d.wmin[a][wid & 3] = anv; }
            __syncthreads();
            if ((tid & 127) == 0) {
                float apm = fmaxf(fmaxf(s.u.d.wmax[a][0], s.u.d.wmax[a][1]),
                                  fmaxf(s.u.d.wmax[a][2], s.u.d.wmax[a][3]));
                float anm = fminf(fminf(s.u.d.wmin[a][0], s.u.d.wmin[a][1]),
                                  fminf(s.u.d.wmin[a][2], s.u.d.wmin[a][3]));
                float dap = (apm > -1e29f) ? apm : 0.f;
                float dan = (anm <  1e29f) ? anm : 1e6f;
                g_tri[h * BATCH + ia] = fmaxf(dap - dan + 0.3f, 0.f);
            }
        } else {
            // ---------------- row-quarter item ----------------------------
            int rq = it - it / 25 - 1;
            int r = rq >> 2, q = rq & 3;
            const float4* lg4 = (const float4*)(logits + (size_t)r * NC) + q * N4Q;
            const float4* sf4 = (const float4*)(soft   + (size_t)r * NC) + q * N4Q;

            float4 vs1 = {0,0,0,0}, vs2 = {0,0,0,0}, vsx = {0,0,0,0};
            float4 vss = {0,0,0,0}, vssx = {0,0,0,0}, vssl = {0,0,0,0};

#define ACC(xx, sv_, L)                                               \
    {   float x = xx, sv = sv_;                                       \
        vsx.L += x;  vss.L += sv;                                     \
        vssx.L = fmaf(sv, x, vssx.L);                                 \
        vssl.L = fmaf(sv, __log2f(fmaxf(sv, 1e-38f)), vssl.L);        \
        float e = ex2(x * C);                                         \
        vs2.L += e;                                                   \
        vs1.L = fmaf(e * e, e, vs1.L); }
#define LANE4(x4, t4) ACC(x4.x, t4.x, x) ACC(x4.y, t4.y, y) \
                      ACC(x4.z, t4.z, z) ACC(x4.w, t4.w, w)

            int i = tid;
            for (; i + 768 < N4Q; i += 1024) {
                float4 x0 = __ldcs(lg4 + i);
                float4 x1 = __ldcs(lg4 + i + 256);
                float4 x2 = __ldcs(lg4 + i + 512);
                float4 x3 = __ldcs(lg4 + i + 768);
                float4 t0 = __ldcs(sf4 + i);
                float4 t1 = __ldcs(sf4 + i + 256);
                float4 t2 = __ldcs(sf4 + i + 512);
                float4 t3 = __ldcs(sf4 + i + 768);
                LANE4(x0, t0) LANE4(x1, t1) LANE4(x2, t2) LANE4(x3, t3)
            }
            for (; i < N4Q; i += 256) {
                float4 x0 = __ldcs(lg4 + i);
                float4 t0 = __ldcs(sf4 + i);
                LANE4(x0, t0)
            }
#undef LANE4
#undef ACC
            float s1  = (vs1.x + vs1.y) + (vs1.z + vs1.w);
            float s2  = (vs2.x + vs2.y) + (vs2.z + vs2.w);
            float sx  = (vsx.x + vsx.y) + (vsx.z + vsx.w);
            float ssv = (vss.x + vss.y) + (vss.z + vss.w);
            float ssx = (vssx.x + vssx.y) + (vssx.z + vssx.w);
            float ssl = (vssl.x + vssl.y) + (vssl.z + vssl.w);
#pragma unroll
            for (int off = 16; off; off >>= 1) {
                s1  += __shfl_down_sync(full, s1,  off);
                s2  += __shfl_down_sync(full, s2,  off);
                sx  += __shfl_down_sync(full, sx,  off);
                ssv += __shfl_down_sync(full, ssv, off);
                ssx += __shfl_down_sync(full, ssx, off);
                ssl += __shfl_down_sync(full, ssl, off);
            }
            if (lane == 0) {
                s.u.sm[0][wid] = s1;  s.u.sm[1][wid] = s2;  s.u.sm[2][wid] = sx;
                s.u.sm[3][wid] = ssv; s.u.sm[4][wid] = ssx; s.u.sm[5][wid] = ssl;
            }
            __syncthreads();
            if (tid == 0) {
#pragma unroll
                for (int k = 0; k < 6; k++) {
                    float a0 = 0.f;
#pragma unroll
                    for (int w = 0; w < 8; w++) a0 += s.u.sm[k][w];
                    g_part[r][q][k] = a0;
                }
            }
        }
        __syncthreads();
    }

    grid_barrier();

    // ================= phase 3: final reduce (block 0 only) ===============
    if (bid != 0) return;
    if (tid == 0) { g_work = 0; __threadfence(); }

    float ceA = 0.f, klwA = 0.f, tri0 = 0.f, tri1 = 0.f;
    for (int r = tid; r < ROWS; r += NTHR) {
        float s1 = 0.f, s2 = 0.f, sx = 0.f, ssv = 0.f, ssx = 0.f, ssl = 0.f;
#pragma unroll
        for (int q = 0; q < 4; q++) {
            s1  += g_part[r][q][0]; s2  += g_part[r][q][1];
            sx  += g_part[r][q][2]; ssv += g_part[r][q][3];
            ssx += g_part[r][q][4]; ssl += g_part[r][q][5];
        }
        float logZ1 = __logf(s1);
        float logZ2 = __logf(s2);
        int   b   = r & (BATCH - 1);
        int   lab = labels[b];
        float xl  = logits[(size_t)r * NC + lab];
        float cev = logZ1 - 0.9f * xl - 0.1f * sx * (1.f / (float)NC);

        float l0 = adv[2 * r], l1 = adv[2 * r + 1];
        float mm = fmaxf(l0, l1);
        float lse = mm + __logf(__expf(l0 - mm) + __expf(l1 - mm));
        float anll = lse - (mod[b] ? l1 : l0);
        ceA += cev + 0.1f * anll;

        float kl = ssl * 0.6931471805599453f - ssx * (1.f / 3.f) + logZ2 * ssv;
        klwA += fminf(kl, 5.0f) * ew[r];
    }
    if (tid < BATCH) { tri0 = g_tri[tid]; tri1 = g_tri[BATCH + tid]; }

#pragma unroll
    for (int off = 16; off; off >>= 1) {
        ceA  += __shfl_down_sync(full, ceA,  off);
        klwA += __shfl_down_sync(full, klwA, off);
        tri0 += __shfl_down_sync(full, tri0, off);
        tri1 += __shfl_down_sync(full, tri1, off);
    }
    if (lane == 0) {
        s.u.fm[0][wid] = ceA; s.u.fm[1][wid] = klwA;
        s.u.fm[2][wid] = tri0; s.u.fm[3][wid] = tri1;
    }
    __syncthreads();
    if (tid == 0) {
        float ceT = 0.f, klwT = 0.f, t0 = 0.f, t1 = 0.f;
#pragma unroll
        for (int w = 0; w < 8; w++) {
            ceT += s.u.fm[0][w]; klwT += s.u.fm[1][w];
            t0  += s.u.fm[2][w]; t1   += s.u.fm[3][w];
        }
        float L_idadv = ceT * (1.f / (float)ROWS);     // includes 0.1*L_adv
        float L_tri   = (t0 + 0.5f * t1) * (1.f / (float)BATCH);
        float L_graph = (epoch_p[0] >= 20) ? klwT * (9.f / (float)ROWS) : 0.f;
        out[0] = L_idadv + L_tri + 0.1f * L_graph;
    }
}

// ============================================================
extern "C" void kernel_launch(void* const* d_in, const int* in_sizes, int n_in,
                              void* d_out, int out_size)
{
    const float* id_logits     = (const float*)d_in[0];
    const float* id_features   = (const float*)d_in[1];
    const float* gray_features = (const float*)d_in[2];
    const float* soft_labels   = (const float*)d_in[3];
    const float* entropy_w     = (const float*)d_in[4];
    const float* adv_logits    = (const float*)d_in[5];
    const int*   labels        = (const int*)d_in[6];
    const int*   mod_labels    = (const int*)d_in[7];
    const int*   epoch         = (const int*)d_in[8];

    mega_kernel<<<NBLK, NTHR>>>(id_logits, soft_labels, entropy_w, labels,
                                adv_logits, mod_labels,
                                id_features, gray_features,
                                epoch, (float*)d_out);
}

// round 5
// speedup vs baseline: 1.9996x; 1.9996x over previous
#include <cuda_runtime.h>
#include <cuda_bf16.h>

#define NC 50000
#define BATCH 128
#define ROWS 768                 // 6 parts * 128
#define DIM 1536                 // 6 * 256
#define N4 12500                 // float4 per row
#define KTILE 128

// ---------------- device scratch (no cudaMalloc allowed) ----------------
__device__ float g_ce[ROWS];            // ce + 0.1*adv_nll per row
__device__ float g_klw[ROWS];
__device__ float g_tri[2 * BATCH];
__device__ float g_F[BATCH * DIM];      // normalized feat rows, fp32
__device__ __align__(16) __nv_bfloat16 g_TtB[DIM * 256]; // transposed targets
__device__ float g_n2[256];
__device__ unsigned g_cnt;              // last-block counter (self-resetting)

__device__ __forceinline__ float ex2(float v) {
    float r;
    asm("ex2.approx.ftz.f32 %0, %1;" : "=f"(r) : "f"(v));
    return r;
}
__device__ __forceinline__ void cpa16(unsigned dst, const void* src) {
    asm volatile("cp.async.ca.shared.global [%0], [%1], 16;" :: "r"(dst), "l"(src));
}

// ============================================================
// Kernel 1 (fused): blocks [0,768) = per-row dual-temp softmax stats
// (branchless, 8 batched LDG.128/iter, per-lane f4 accumulators);
// blocks [768,1024) = feature normalize + bf16 transpose prep.
// launch_bounds(256,3): reg cap 85 so the load batch stays in flight.
// ============================================================
__global__ __launch_bounds__(256, 3) void fused1_kernel(
    const float* __restrict__ logits, const float* __restrict__ soft,
    const float* __restrict__ ew,     const int*   __restrict__ labels,
    const float* __restrict__ adv,    const int*   __restrict__ mod,
    const float* __restrict__ idf,    const float* __restrict__ gf)
{
    const int tid = threadIdx.x;
    const int lane = tid & 31, wid = tid >> 5;
    const unsigned full = 0xffffffffu;

    if (blockIdx.x >= ROWS) {
        // ---------------- prep path ----------------
        int j = blockIdx.x - ROWS;          // 0..255
        const float* src = (j < BATCH) ? idf : gf;
        int b = j & (BATCH - 1);

        float v[6];
        float sq = 0.f;
#pragma unroll
        for (int p = 0; p < 6; p++) {
            float x = src[(size_t)(p * BATCH + b) * 256 + tid];
            v[p] = x;
            sq = fmaf(x, x, sq);
        }
#pragma unroll
        for (int off = 16; off; off >>= 1) sq += __shfl_down_sync(full, sq, off);
        __shared__ float wsum[8];
        if (lane == 0) wsum[wid] = sq;
        __syncthreads();
        float tot = 0.f;
#pragma unroll
        for (int w = 0; w < 8; w++) tot += wsum[w];
        float rn = rsqrtf(tot);
#pragma unroll
        for (int p = 0; p < 6; p++) {
            int d = p * 256 + tid;
            float nv = v[p] * rn;
            g_TtB[(size_t)d * 256 + j] = __float2bfloat16_rn(nv);
            if (j < BATCH) g_F[(size_t)b * DIM + d] = nv;
        }
        if (tid == 0) g_n2[j] = tot * rn * rn;
        return;
    }

    // ---------------- row path ----------------
    const int r = blockIdx.x;
    const float4* lg4 = (const float4*)(logits + (size_t)r * NC);
    const float4* sf4 = (const float4*)(soft   + (size_t)r * NC);
    const float C = 0.48089834696298783f;   // log2(e)/3

    float4 vs1 = {0,0,0,0}, vs2 = {0,0,0,0}, vsx = {0,0,0,0};
    float4 vss = {0,0,0,0}, vssx = {0,0,0,0}, vssl = {0,0,0,0};

#define ACC(xx, sv_, L)                                               \
    {   float x = xx, sv = sv_;                                       \
        vsx.L += x;  vss.L += sv;                                     \
        vssx.L = fmaf(sv, x, vssx.L);                                 \
        vssl.L = fmaf(sv, __log2f(fmaxf(sv, 1e-38f)), vssl.L);        \
        float e = ex2(x * C);                                         \
        vs2.L += e;                                                   \
        vs1.L = fmaf(e * e, e, vs1.L); }
#define LANE4(x4, t4) ACC(x4.x, t4.x, x) ACC(x4.y, t4.y, y) \
                      ACC(x4.z, t4.z, z) ACC(x4.w, t4.w, w)

    int i = tid;
    for (; i + 768 < N4; i += 1024) {
        float4 x0 = __ldcs(lg4 + i);
        float4 x1 = __ldcs(lg4 + i + 256);
        float4 x2 = __ldcs(lg4 + i + 512);
        float4 x3 = __ldcs(lg4 + i + 768);
        float4 t0 = __ldcs(sf4 + i);
        float4 t1 = __ldcs(sf4 + i + 256);
        float4 t2 = __ldcs(sf4 + i + 512);
        float4 t3 = __ldcs(sf4 + i + 768);
        LANE4(x0, t0) LANE4(x1, t1) LANE4(x2, t2) LANE4(x3, t3)
    }
    for (; i < N4; i += 256) {
        float4 x0 = __ldcs(lg4 + i);
        float4 t0 = __ldcs(sf4 + i);
        LANE4(x0, t0)
    }
#undef LANE4
#undef ACC

    float s1  = (vs1.x + vs1.y) + (vs1.z + vs1.w);
    float s2  = (vs2.x + vs2.y) + (vs2.z + vs2.w);
    float sx  = (vsx.x + vsx.y) + (vsx.z + vsx.w);
    float ssv = (vss.x + vss.y) + (vss.z + vss.w);
    float ssx = (vssx.x + vssx.y) + (vssx.z + vssx.w);
    float ssl = (vssl.x + vssl.y) + (vssl.z + vssl.w);

#pragma unroll
    for (int off = 16; off; off >>= 1) {
        s1  += __shfl_down_sync(full, s1,  off);
        s2  += __shfl_down_sync(full, s2,  off);
        sx  += __shfl_down_sync(full, sx,  off);
        ssv += __shfl_down_sync(full, ssv, off);
        ssx += __shfl_down_sync(full, ssx, off);
        ssl += __shfl_down_sync(full, ssl, off);
    }

    __shared__ float sm[6][8];
    if (lane == 0) {
        sm[0][wid] = s1;  sm[1][wid] = s2;  sm[2][wid] = sx;
        sm[3][wid] = ssv; sm[4][wid] = ssx; sm[5][wid] = ssl;
    }
    __syncthreads();

    if (tid == 0) {
        s1 = 0.f; s2 = 0.f; sx = 0.f; ssv = 0.f; ssx = 0.f; ssl = 0.f;
#pragma unroll
        for (int w = 0; w < 8; w++) {
            s1 += sm[0][w]; s2 += sm[1][w]; sx += sm[2][w];
            ssv += sm[3][w]; ssx += sm[4][w]; ssl += sm[5][w];
        }
        float logZ1 = __logf(s1);
        float logZ2 = __logf(s2);

        int   b   = r & (BATCH - 1);
        int   lab = labels[b];
        float xl  = logits[(size_t)r * NC + lab];
        float ce  = logZ1 - 0.9f * xl - 0.1f * sx * (1.f / (float)NC);

        float l0 = adv[2 * r], l1 = adv[2 * r + 1];
        float mm = fmaxf(l0, l1);
        float lse = mm + __logf(__expf(l0 - mm) + __expf(l1 - mm));
        float anll = lse - (mod[b] ? l1 : l0);
        g_ce[r] = ce + 0.1f * anll;

        float kl = ssl * 0.6931471805599453f - ssx * (1.f / 3.f) + logZ2 * ssv;
        g_klw[r] = fminf(kl, 5.0f) * ew[r];
    }
}

// ============================================================
// Kernel 2: 128 blocks = (64 anchor-pairs) x (2 target halves).
// cp.async-staged K tiles (128 k x 128 targets bf16 = 32KB) + anchor tiles;
// compute from smem (LDS.64, conflict-free). No data registers needed for
// loads -> immune to ptxas register capping. Last block does final reduce.
// ============================================================
__global__ __launch_bounds__(256) void dist_kernel(
    const int* __restrict__ labels,
    const int* __restrict__ epoch_p,
    float*     __restrict__ out)
{
    __shared__ __align__(16) __nv_bfloat16 Ts[KTILE][128];  // 32 KB
    __shared__ __align__(16) float As[2][KTILE];            // 1 KB
    __shared__ float red[8][2][128];                        // 8 KB
    __shared__ float wmax[2][8], wmin[2][8];
    __shared__ bool  s_last;

    const int tid = threadIdx.x;
    const int lane = tid & 31, wid = tid >> 5;
    const unsigned full = 0xffffffffu;

    int p  = blockIdx.x >> 1;
    int h  = blockIdx.x & 1;
    int i0 = p * 2;

    unsigned ts_base = (unsigned)__cvta_generic_to_shared(Ts);
    unsigned as_base = (unsigned)__cvta_generic_to_shared(As);

    float c00 = 0.f, c01 = 0.f, c02 = 0.f, c03 = 0.f;
    float c10 = 0.f, c11 = 0.f, c12 = 0.f, c13 = 0.f;

    const int trow  = tid >> 1;               // 0..127: k row within tile
    const int tcol  = (tid & 1) * 128;        // byte offset within 256B half-row

#pragma unroll 1
    for (int tile = 0; tile < DIM / KTILE; tile++) {
        int k0 = tile * KTILE;
        __syncthreads();                      // previous compute done

        // stage target tile: row k -> bytes [k*512 + h*256, +256)
        {
            const char* gsrc = (const char*)g_TtB
                             + (size_t)(k0 + trow) * 512 + h * 256 + tcol;
            unsigned sdst = ts_base + trow * 256 + tcol;
#pragma unroll
            for (int c8 = 0; c8 < 8; c8++)
                cpa16(sdst + c8 * 16, gsrc + c8 * 16);
        }
        // stage anchor tiles (2 x 128 floats = 64 x 16B chunks)
        if (tid < 64) {
            int a  = tid >> 5;
            int ch = tid & 31;
            const char* gsrc = (const char*)(g_F + (size_t)(i0 + a) * DIM + k0)
                             + ch * 16;
            cpa16(as_base + (a * KTILE + ch * 4) * 4, gsrc);
        }
        asm volatile("cp.async.commit_group;");
        asm volatile("cp.async.wait_group 0;" ::: "memory");
        __syncthreads();

        // compute: warp w handles k in [w*16, w*16+16); lane -> 4 targets
        int kl0 = wid * 16;
#pragma unroll
        for (int kk = 0; kk < 16; kk++) {
            int k = kl0 + kk;
            uint2 t = *(const uint2*)((const char*)Ts + k * 256 + lane * 8);
            float f0 = __uint_as_float(t.x << 16);
            float f1 = __uint_as_float(t.x & 0xffff0000u);
            float f2 = __uint_as_float(t.y << 16);
            float f3 = __uint_as_float(t.y & 0xffff0000u);
            float A0 = As[0][k], A1 = As[1][k];
            c00 = fmaf(A0, f0, c00); c01 = fmaf(A0, f1, c01);
            c02 = fmaf(A0, f2, c02); c03 = fmaf(A0, f3, c03);
            c10 = fmaf(A1, f0, c10); c11 = fmaf(A1, f1, c11);
            c12 = fmaf(A1, f2, c12); c13 = fmaf(A1, f3, c13);
        }
    }

    ((float4*)red[wid][0])[lane] = make_float4(c00, c01, c02, c03);
    ((float4*)red[wid][1])[lane] = make_float4(c10, c11, c12, c13);
    __syncthreads();

    // mining: threads 0..127 -> anchor i0, 128..255 -> anchor i0+1
    int a  = tid >> 7;
    int jl = tid & 127;
    int ia = i0 + a;
    int jglob = h * 128 + jl;

    float dot = 0.f;
#pragma unroll
    for (int sl = 0; sl < 8; sl++) dot += red[sl][a][jl];
    float sqv = g_n2[ia] + g_n2[jglob] - 2.f * dot;
    float dj  = sqrtf(fmaxf(sqv, 0.f) + 1e-12f);

    bool eq  = (labels[ia] == labels[jl]);
    bool pos = h ? eq : (eq && (jl != ia));
    float apv = pos   ? dj : -1e30f;
    float anv = (!eq) ? dj :  1e30f;
#pragma unroll
    for (int off = 16; off; off >>= 1) {
        apv = fmaxf(apv, __shfl_down_sync(full, apv, off));
        anv = fminf(anv, __shfl_down_sync(full, anv, off));
    }
    if (lane == 0) { wmax[a][wid & 3] = apv; wmin[a][wid & 3] = anv; }
    __syncthreads();

    if ((tid & 127) == 0) {
        float apm = fmaxf(fmaxf(wmax[a][0], wmax[a][1]), fmaxf(wmax[a][2], wmax[a][3]));
        float anm = fminf(fminf(wmin[a][0], wmin[a][1]), fminf(wmin[a][2], wmin[a][3]));
        float dap = (apm > -1e29f) ? apm : 0.f;
        float dan = (anm <  1e29f) ? anm : 1e6f;
        g_tri[h * BATCH + ia] = fmaxf(dap - dan + 0.3f, 0.f);
    }
    __syncthreads();

    // ---- last-block-done final reduce ----
    if (tid == 0) {
        __threadfence();
        unsigned v = atomicAdd(&g_cnt, 1);
        s_last = (v == (unsigned)(gridDim.x - 1));
    }
    __syncthreads();
    if (!s_last) return;
    if (tid == 0) { g_cnt = 0; __threadfence(); }

    float ceA = 0.f, klwA = 0.f, tri0 = 0.f, tri1 = 0.f;
    for (int r = tid; r < ROWS; r += 256) {
        ceA  += g_ce[r];
        klwA += g_klw[r];
    }
    if (tid < BATCH) { tri0 = g_tri[tid]; tri1 = g_tri[BATCH + tid]; }

#pragma unroll
    for (int off = 16; off; off >>= 1) {
        ceA  += __shfl_down_sync(full, ceA,  off);
        klwA += __shfl_down_sync(full, klwA, off);
        tri0 += __shfl_down_sync(full, tri0, off);
        tri1 += __shfl_down_sync(full, tri1, off);
    }
    __shared__ float fm[4][8];
    if (lane == 0) {
        fm[0][wid] = ceA; fm[1][wid] = klwA; fm[2][wid] = tri0; fm[3][wid] = tri1;
    }
    __syncthreads();

    if (tid == 0) {
        float ceT = 0.f, klwT = 0.f, t0 = 0.f, t1 = 0.f;
#pragma unroll
        for (int w = 0; w < 8; w++) {
            ceT += fm[0][w]; klwT += fm[1][w]; t0 += fm[2][w]; t1 += fm[3][w];
        }
        float L_idadv = ceT * (1.f / (float)ROWS);   // includes 0.1*L_adv
        float L_tri   = (t0 + 0.5f * t1) * (1.f / (float)BATCH);
        float L_graph = (epoch_p[0] >= 20) ? klwT * (9.f / (float)ROWS) : 0.f;
        out[0] = L_idadv + L_tri + 0.1f * L_graph;
    }
}

// ============================================================
extern "C" void kernel_launch(void* const* d_in, const int* in_sizes, int n_in,
                              void* d_out, int out_size)
{
    const float* id_logits     = (const float*)d_in[0];
    const float* id_features   = (const float*)d_in[1];
    const float* gray_features = (const float*)d_in[2];
    const float* soft_labels   = (const float*)d_in[3];
    const float* entropy_w     = (const float*)d_in[4];
    const float* adv_logits    = (const float*)d_in[5];
    const int*   labels        = (const int*)d_in[6];
    const int*   mod_labels    = (const int*)d_in[7];
    const int*   epoch         = (const int*)d_in[8];

    fused1_kernel<<<ROWS + 256, 256>>>(id_logits, soft_labels, entropy_w, labels,
                                       adv_logits, mod_labels,
                                       id_features, gray_features);
    dist_kernel<<<BATCH, 256>>>(labels, epoch, (float*)d_out);
}